// round 6
// baseline (speedup 1.0000x reference)
#include <cuda_runtime.h>
#include <cstdint>

// QuantileLoss: mean over [N,5] loss built from preds[N,5], target[N,3].
// R6: persistent grid + double-buffered cp.async with SMALL tiles.
//     Tile = 128 quads = 16KB/buffer, 2 buffers = 32KB -> 6 CTAs/SM (75% occ)
//     AND intra-block overlap (wait_group 1). 12 tiles in flight per SM.

__global__ void zero_out_kernel(float* out) {
    if (threadIdx.x == 0) out[0] = 0.0f;
}

__device__ __forceinline__ void cp_async16(uint32_t saddr, const void* gptr) {
    asm volatile("cp.async.cg.shared.global [%0], [%1], 16;\n"
                 :: "r"(saddr), "l"(gptr));
}

__device__ __forceinline__ float row_loss(
    float p0, float p1, float p2, float p3, float p4,
    float t0, float t1, float t2)
{
    float d0 = p0 - t0;
    float d1 = p1 - t1;
    float d2 = p2 - t2;
    float main_mse = d0 * d0 + d1 * d1 + d2 * d2;

    float pen = (p4 - t2) * 4.0f;

    float lo_th = t2 * 0.95f;
    float lo_d  = p3 - lo_th;
    float lower = (p3 > p2) ? pen : ((p3 > lo_th) ? 0.0f : lo_d * lo_d);

    float up_th = t2 * 1.05f;
    float up_d  = p4 - up_th;
    float upper = (p4 < p2) ? pen : ((p4 < up_th) ? 0.0f : up_d * up_d);

    return main_mse + lower + upper;
}

// Buffer layout (1024 float4): [0..639] preds (128 quads * 5), [640..1023] target (128*3).
// Stage loads: 4 cp.async per thread, slots tid + k*256.
__device__ __forceinline__ void stage_tile(uint32_t buf_saddr,
                                           const float4* __restrict__ preds4,
                                           const float4* __restrict__ tgt4,
                                           int tile, int tid)
{
    const float4* pg = preds4 + (size_t)tile * 640;
    const float4* tg = tgt4   + (size_t)tile * 384;
    #pragma unroll
    for (int k = 0; k < 4; k++) {
        int s = tid + k * 256;
        const float4* src = (s < 640) ? (pg + s) : (tg + (s - 640));
        cp_async16(buf_saddr + (uint32_t)s * 16u, src);
    }
    asm volatile("cp.async.commit_group;\n" ::: "memory");
}

__global__ void __launch_bounds__(256)
quantile_loss_kernel(const float4* __restrict__ preds4,
                     const float4* __restrict__ tgt4,
                     const float*  __restrict__ preds,
                     const float*  __restrict__ target,
                     float* __restrict__ out,
                     int nquads, int n_rows, float inv_count)
{
    extern __shared__ float4 sh[];   // 2 buffers * 1024 float4 = 32 KB
    const int tid = threadIdx.x;
    const uint32_t sbase = (uint32_t)__cvta_generic_to_shared(sh);

    const int ntiles = nquads >> 7;          // full 128-quad tiles
    float s = 0.0f;

    // prologue: prefetch first tile into buffer 0
    int tile = blockIdx.x;
    if (tile < ntiles)
        stage_tile(sbase, preds4, tgt4, tile, tid);

    const int q    = tid >> 1;               // quad within tile (0..127)
    const bool odd = (tid & 1);

    int buf = 0;
    for (; tile < ntiles; tile += gridDim.x) {
        int next = tile + gridDim.x;
        if (next < ntiles) {
            stage_tile(sbase + (uint32_t)(buf ^ 1) * 1024u * 16u,
                       preds4, tgt4, next, tid);
            asm volatile("cp.async.wait_group 1;\n" ::: "memory");
        } else {
            asm volatile("cp.async.wait_group 0;\n" ::: "memory");
        }
        __syncthreads();   // current buffer landed for all threads

        const float4* b = sh + buf * 1024;
        if (!odd) {
            // rows 0,1 of quad q
            float4 P0 = b[q * 5 + 0];
            float4 P1 = b[q * 5 + 1];
            float4 P2 = b[q * 5 + 2];
            float4 G0 = b[640 + q * 3 + 0];
            float4 G1 = b[640 + q * 3 + 1];
            s += row_loss(P0.x, P0.y, P0.z, P0.w, P1.x, G0.x, G0.y, G0.z);
            s += row_loss(P1.y, P1.z, P1.w, P2.x, P2.y, G0.w, G1.x, G1.y);
        } else {
            // rows 2,3 of quad q
            float4 P2 = b[q * 5 + 2];
            float4 P3 = b[q * 5 + 3];
            float4 P4 = b[q * 5 + 4];
            float4 G1 = b[640 + q * 3 + 1];
            float4 G2 = b[640 + q * 3 + 2];
            s += row_loss(P2.z, P2.w, P3.x, P3.y, P3.z, G1.z, G1.w, G2.x);
            s += row_loss(P3.w, P4.x, P4.y, P4.z, P4.w, G2.y, G2.z, G2.w);
        }

        buf ^= 1;
        __syncthreads();   // compute reads done before this buffer is reloaded
    }

    // remainder quads (nquads % 128): block 0, direct loads
    if (blockIdx.x == 0) {
        int rq = (ntiles << 7) + tid;
        if (rq < nquads) {
            float4 p0 = preds4[rq * 5 + 0];
            float4 p1 = preds4[rq * 5 + 1];
            float4 p2 = preds4[rq * 5 + 2];
            float4 p3 = preds4[rq * 5 + 3];
            float4 p4 = preds4[rq * 5 + 4];
            float4 g0 = tgt4[rq * 3 + 0];
            float4 g1 = tgt4[rq * 3 + 1];
            float4 g2 = tgt4[rq * 3 + 2];
            s += row_loss(p0.x, p0.y, p0.z, p0.w, p1.x, g0.x, g0.y, g0.z);
            s += row_loss(p1.y, p1.z, p1.w, p2.x, p2.y, g0.w, g1.x, g1.y);
            s += row_loss(p2.z, p2.w, p3.x, p3.y, p3.z, g1.z, g1.w, g2.x);
            s += row_loss(p3.w, p4.x, p4.y, p4.z, p4.w, g2.y, g2.z, g2.w);
        }
        // tail rows (n_rows % 4)
        if (tid == 0) {
            for (int r = nquads * 4; r < n_rows; r++) {
                s += row_loss(preds[r * 5 + 0], preds[r * 5 + 1], preds[r * 5 + 2],
                              preds[r * 5 + 3], preds[r * 5 + 4],
                              target[r * 3 + 0], target[r * 3 + 1], target[r * 3 + 2]);
            }
        }
    }

    // intra-block reduce
    #pragma unroll
    for (int off = 16; off > 0; off >>= 1)
        s += __shfl_down_sync(0xFFFFFFFFu, s, off);

    __syncthreads();
    float* ws = (float*)sh;
    int lane = tid & 31;
    int wid  = tid >> 5;
    if (lane == 0) ws[wid] = s;
    __syncthreads();

    if (wid == 0) {
        s = (lane < 8) ? ws[lane] : 0.0f;
        #pragma unroll
        for (int off = 4; off > 0; off >>= 1)
            s += __shfl_down_sync(0xFFFFFFFFu, s, off);
        if (lane == 0)
            atomicAdd(out, s * inv_count);
    }
}

extern "C" void kernel_launch(void* const* d_in, const int* in_sizes, int n_in,
                              void* d_out, int out_size)
{
    const float* preds  = (const float*)d_in[0];
    const float* target = (const float*)d_in[1];
    float* out = (float*)d_out;

    int n_rows = in_sizes[0] / 5;
    int nquads = n_rows / 4;
    float inv_count = 1.0f / (5.0f * (float)n_rows);

    const int smem_bytes = 2 * 1024 * 16;   // 32 KB
    cudaFuncSetAttribute(quantile_loss_kernel,
                         cudaFuncAttributeMaxDynamicSharedMemorySize, smem_bytes);

    zero_out_kernel<<<1, 32>>>(out);

    int ntiles = nquads >> 7;
    int blocks = 6 * 148;                    // persistent: 6 CTAs per SM
    if (ntiles > 0 && ntiles < blocks) blocks = ntiles;
    if (blocks < 1) blocks = 1;

    quantile_loss_kernel<<<blocks, 256, smem_bytes>>>(
        (const float4*)preds, (const float4*)target,
        preds, target, out, nquads, n_rows, inv_count);
}

// round 7
// speedup vs baseline: 1.0794x; 1.0794x over previous
#include <cuda_runtime.h>
#include <cstdint>

// QuantileLoss: mean over [N,5] loss built from preds[N,5], target[N,3].
// R7: R4 (single-buffered cp.async staging, best @22.7us, DRAM 76.5%)
//     + __launch_bounds__(256,7): R4 was register-limited (regs=40 -> 6 CTA/SM,
//     occ 67.8%). Cap regs to 36 -> 7 CTA/SM (87.5% occ), smem still fits
//     (7 x 32KB = 224KB <= 228KB).

__global__ void zero_out_kernel(float* out) {
    if (threadIdx.x == 0) out[0] = 0.0f;
}

__device__ __forceinline__ void cp_async16(uint32_t saddr, const void* gptr) {
    asm volatile("cp.async.cg.shared.global [%0], [%1], 16;\n"
                 :: "r"(saddr), "l"(gptr));
}

__device__ __forceinline__ float row_loss(
    float p0, float p1, float p2, float p3, float p4,
    float t0, float t1, float t2)
{
    float d0 = p0 - t0;
    float d1 = p1 - t1;
    float d2 = p2 - t2;
    float main_mse = d0 * d0 + d1 * d1 + d2 * d2;

    float pen = (p4 - t2) * 4.0f;

    float lo_th = t2 * 0.95f;
    float lo_d  = p3 - lo_th;
    float lower = (p3 > p2) ? pen : ((p3 > lo_th) ? 0.0f : lo_d * lo_d);

    float up_th = t2 * 1.05f;
    float up_d  = p4 - up_th;
    float upper = (p4 < p2) ? pen : ((p4 < up_th) ? 0.0f : up_d * up_d);

    return main_mse + lower + upper;
}

__device__ __forceinline__ float quad_rows(
    float4 p0, float4 p1, float4 p2, float4 p3, float4 p4,
    float4 g0, float4 g1, float4 g2)
{
    float s;
    s  = row_loss(p0.x, p0.y, p0.z, p0.w, p1.x, g0.x, g0.y, g0.z);
    s += row_loss(p1.y, p1.z, p1.w, p2.x, p2.y, g0.w, g1.x, g1.y);
    s += row_loss(p2.z, p2.w, p3.x, p3.y, p3.z, g1.z, g1.w, g2.x);
    s += row_loss(p3.w, p4.x, p4.y, p4.z, p4.w, g2.y, g2.z, g2.w);
    return s;
}

// Tile: 256 quads (= 1024 rows) per block of 256 threads.
// smem: 1280 float4 preds + 768 float4 target = 2048 float4 = 32 KB exactly.
__global__ void __launch_bounds__(256, 7)
quantile_loss_kernel(const float4* __restrict__ preds4,
                     const float4* __restrict__ tgt4,
                     const float*  __restrict__ preds,
                     const float*  __restrict__ target,
                     float* __restrict__ out,
                     int nquads, int n_rows, float inv_count)
{
    __shared__ float4 sh[2048];   // [0..1279] preds, [1280..2047] target

    const int tid = threadIdx.x;
    const int qb  = blockIdx.x << 8;   // 256 quads per block
    float s = 0.0f;

    if (qb + 256 <= nquads) {
        // ---- fast path: fully-coalesced cp.async staging ----
        uint32_t sbase = (uint32_t)__cvta_generic_to_shared(sh);
        const float4* pg = preds4 + (size_t)qb * 5;
        const float4* tg = tgt4   + (size_t)qb * 3;

        #pragma unroll
        for (int k = 0; k < 5; k++)
            cp_async16(sbase + (uint32_t)(k * 256 + tid) * 16u, pg + k * 256 + tid);
        #pragma unroll
        for (int k = 0; k < 3; k++)
            cp_async16(sbase + (uint32_t)(1280 + k * 256 + tid) * 16u, tg + k * 256 + tid);

        asm volatile("cp.async.commit_group;\n" ::: "memory");
        asm volatile("cp.async.wait_group 0;\n" ::: "memory");
        __syncthreads();

        // strided smem reads: 80B / 48B lane strides are conflict-free
        float4 p0 = sh[tid * 5 + 0];
        float4 p1 = sh[tid * 5 + 1];
        float4 p2 = sh[tid * 5 + 2];
        float4 p3 = sh[tid * 5 + 3];
        float4 p4 = sh[tid * 5 + 4];
        float4 g0 = sh[1280 + tid * 3 + 0];
        float4 g1 = sh[1280 + tid * 3 + 1];
        float4 g2 = sh[1280 + tid * 3 + 2];

        s = quad_rows(p0, p1, p2, p3, p4, g0, g1, g2);
    } else {
        // ---- partial tile: direct guarded loads (rare) ----
        int q = qb + tid;
        if (q < nquads) {
            float4 p0 = preds4[q * 5 + 0];
            float4 p1 = preds4[q * 5 + 1];
            float4 p2 = preds4[q * 5 + 2];
            float4 p3 = preds4[q * 5 + 3];
            float4 p4 = preds4[q * 5 + 4];
            float4 g0 = tgt4[q * 3 + 0];
            float4 g1 = tgt4[q * 3 + 1];
            float4 g2 = tgt4[q * 3 + 2];
            s = quad_rows(p0, p1, p2, p3, p4, g0, g1, g2);
        }
    }

    // tail rows (n_rows % 4) handled by one thread
    if (blockIdx.x == 0 && threadIdx.x == 0) {
        for (int r = nquads * 4; r < n_rows; r++) {
            s += row_loss(preds[r * 5 + 0], preds[r * 5 + 1], preds[r * 5 + 2],
                          preds[r * 5 + 3], preds[r * 5 + 4],
                          target[r * 3 + 0], target[r * 3 + 1], target[r * 3 + 2]);
        }
    }

    // intra-block reduce: warp shuffle -> smem (reuse tile) -> warp 0
    #pragma unroll
    for (int off = 16; off > 0; off >>= 1)
        s += __shfl_down_sync(0xFFFFFFFFu, s, off);

    __syncthreads();                      // all smem tile reads done
    float* ws = (float*)sh;               // reuse tile as warp-sum scratch
    int lane = tid & 31;
    int wid  = tid >> 5;
    if (lane == 0) ws[wid] = s;
    __syncthreads();

    if (wid == 0) {
        s = (lane < 8) ? ws[lane] : 0.0f;
        #pragma unroll
        for (int off = 4; off > 0; off >>= 1)
            s += __shfl_down_sync(0xFFFFFFFFu, s, off);
        if (lane == 0)
            atomicAdd(out, s * inv_count);
    }
}

extern "C" void kernel_launch(void* const* d_in, const int* in_sizes, int n_in,
                              void* d_out, int out_size)
{
    const float* preds  = (const float*)d_in[0];
    const float* target = (const float*)d_in[1];
    float* out = (float*)d_out;

    int n_rows = in_sizes[0] / 5;
    int nquads = n_rows / 4;
    float inv_count = 1.0f / (5.0f * (float)n_rows);

    zero_out_kernel<<<1, 32>>>(out);

    const int threads = 256;
    int blocks = (nquads + 255) / 256;
    if (blocks < 1) blocks = 1;

    quantile_loss_kernel<<<blocks, threads>>>(
        (const float4*)preds, (const float4*)target,
        preds, target, out, nquads, n_rows, inv_count);
}